// round 11
// baseline (speedup 1.0000x reference)
#include <cuda_runtime.h>
#include <cuda_fp16.h>
#include <math.h>

// Problem constants
#define Bb 4
#define Nn 16
#define Gg 64            // Bb*Nn
#define Ll 2048
#define Ee 32768
#define C0 64
#define Cc 128
#define C2 256
#define EPSf 1e-5

typedef unsigned long long ull;

// packed f32x2 FMA: d = a*b + d (elementwise on 2 packed floats)
#define FFMA2(d, a, b) asm("fma.rn.f32x2 %0, %1, %2, %3;" : "=l"(d) : "l"(a), "l"(b), "l"(d))

// ---------------- scratch (static device globals; no allocation) ----------------
__device__ __half g_h0h [Gg*Ll*C0];   // transposed x        [g,l,64] fp16
__device__ __half g_hWh [Gg*Ll*Cc];   // GEMM out pre-agg    [g,l,128] fp16
__device__ float  g_a   [Gg*Ll*Cc];   // post-agg (+bias)    [g,l,128]
__device__ float  g_U   [Bb*Ll*Cc];   // act(amax) @ W_up    [b,l,128]
__device__ float  g_amax[Bb*Ll*Cc];   // max over n of a     [b,l,128]

__device__ ull g_Wp1[(C0/2)*Cc];     // packed W1  (32 kpairs x 128)
__device__ ull g_Wp2[(C2/2)*Cc];     // packed W2  (128 kpairs x 128; [0:64)=low, [64:128)=up)
__device__ ull g_Wp3[(C2/2)*Cc];     // packed W3

__device__ double g_sum[C2], g_sumsq[C2];
__device__ float  g_scale[C2], g_shift[C2];

__device__ int   g_rowptr[Ll+1];
__device__ int   g_col[Ee];
__device__ float g_enorm[Ee];
__device__ float g_selfnorm[Ll];

// ---------------- fused graph build: detect dtype + count + scan + fill ----------------
__global__ __launch_bounds__(1024) void graph_build(const unsigned int* __restrict__ w) {
    __shared__ int   s_any;
    __shared__ int   s_cnt[Ll];
    __shared__ int   s_base[Ll];
    __shared__ float s_dinv[Ll];
    __shared__ int   s_wsum[32];
    int tid = threadIdx.x;

    if (tid == 0) s_any = 0;
    s_cnt[tid] = 0; s_cnt[tid + 1024] = 0;
    __syncthreads();

    // dtype detect: int64 layout with values<2048 -> all odd u32 words zero
    int any = 0;
    for (int i = 2 * tid + 1; i < 16384; i += 2048)
        if (w[i] != 0u) any = 1;
    if (any) s_any = 1;
    __syncthreads();
    const int is64 = (s_any == 0);

    // count in-degree (smem atomics)
    for (int e = tid; e < Ee; e += 1024) {
        int d = (is64 ? (int)w[2 * (Ee + e)] : (int)w[Ee + e]) & (Ll - 1);
        atomicAdd(&s_cnt[d], 1);
    }
    __syncthreads();

    // exclusive scan over 2048 counts (2 per thread)
    int n0 = 2 * tid, n1 = 2 * tid + 1;
    int v0 = s_cnt[n0], v1 = s_cnt[n1];
    int s = v0 + v1;
    int lane = tid & 31, wid = tid >> 5;
    int own = s;
    #pragma unroll
    for (int off = 1; off < 32; off <<= 1) {
        int t = __shfl_up_sync(0xffffffffu, s, off);
        if (lane >= off) s += t;
    }
    if (lane == 31) s_wsum[wid] = s;
    __syncthreads();
    if (wid == 0) {
        int t = s_wsum[lane];
        int o = t;
        #pragma unroll
        for (int off = 1; off < 32; off <<= 1) {
            int u = __shfl_up_sync(0xffffffffu, t, off);
            if (lane >= off) t += u;
        }
        s_wsum[lane] = t - o;   // exclusive warp offsets
    }
    __syncthreads();
    int run = s_wsum[wid] + s - own;    // exclusive prefix for node n0

    g_rowptr[n0] = run;  s_base[n0] = run;
    float deg0 = (float)v0 + 2.0f;
    s_dinv[n0] = rsqrtf(deg0); g_selfnorm[n0] = 2.0f / deg0;
    int run1 = run + v0;
    g_rowptr[n1] = run1; s_base[n1] = run1;
    float deg1 = (float)v1 + 2.0f;
    s_dinv[n1] = rsqrtf(deg1); g_selfnorm[n1] = 2.0f / deg1;
    if (tid == 1023) g_rowptr[Ll] = run1 + v1;
    s_cnt[n0] = 0; s_cnt[n1] = 0;   // reuse as fill cursors
    __syncthreads();

    // fill CSR
    for (int e = tid; e < Ee; e += 1024) {
        int sN = (is64 ? (int)w[2 * e]        : (int)w[e])        & (Ll - 1);
        int d  = (is64 ? (int)w[2 * (Ee + e)] : (int)w[Ee + e])   & (Ll - 1);
        int pos = s_base[d] + atomicAdd(&s_cnt[d], 1);
        g_col[pos] = sN;
        g_enorm[pos] = s_dinv[sN] * s_dinv[d];
    }
}

// ---------------- pack weights into u64 k-pairs ----------------
__global__ void pack_weights(const float* __restrict__ W1,
                             const float* __restrict__ W2,
                             const float* __restrict__ W3) {
    int flat = blockIdx.x * blockDim.x + threadIdx.x;   // 0 .. 288*128-1
    const int N1 = (C0/2) * Cc;          // 4096
    const int N2 = (C2/2) * Cc;          // 16384
    if (flat < N1) {
        int kp = flat / Cc, c = flat % Cc;
        unsigned lo = __float_as_uint(W1[(2*kp)   * Cc + c]);
        unsigned hi = __float_as_uint(W1[(2*kp+1) * Cc + c]);
        g_Wp1[flat] = (ull)lo | ((ull)hi << 32);
    } else if (flat < N1 + N2) {
        int f = flat - N1;
        int kp = f / Cc, c = f % Cc;
        unsigned lo = __float_as_uint(W2[(2*kp)   * Cc + c]);
        unsigned hi = __float_as_uint(W2[(2*kp+1) * Cc + c]);
        g_Wp2[f] = (ull)lo | ((ull)hi << 32);
    } else if (flat < N1 + 2*N2) {
        int f = flat - N1 - N2;
        int kp = f / Cc, c = f % Cc;
        unsigned lo = __float_as_uint(W3[(2*kp)   * Cc + c]);
        unsigned hi = __float_as_uint(W3[(2*kp+1) * Cc + c]);
        g_Wp3[f] = (ull)lo | ((ull)hi << 32);
    }
}

// ---------------- transpose x [b,n,c,l] -> g_h0h [g,l,c] fp16 ----------------
__global__ void transpose_x(const float* __restrict__ x) {
    __shared__ float t[32][33];
    int g = blockIdx.z, c0 = blockIdx.y * 32, l0 = blockIdx.x * 32;
    int tx = threadIdx.x, ty = threadIdx.y;
    #pragma unroll
    for (int i = 0; i < 32; i += 8) {
        int c = c0 + ty + i, l = l0 + tx;
        t[ty + i][tx] = x[((size_t)(g * C0 + c)) * Ll + l];
    }
    __syncthreads();
    #pragma unroll
    for (int i = 0; i < 32; i += 8) {
        int l = l0 + ty + i, c = c0 + tx;
        g_h0h[((size_t)g * Ll + l) * C0 + c] = __float2half(t[tx][ty + i]);
    }
}

// ---------------- fused layer-1: a = (A h0) @ W1 + b1  (gather in staging) ----------------
__global__ __launch_bounds__(128) void gemm1_fused(const float* __restrict__ bias) {
    if (blockIdx.x == 0) {     // zero BN stat accumulators for layer 1
        g_sum[threadIdx.x] = 0.0;       g_sumsq[threadIdx.x] = 0.0;
        g_sum[Cc + threadIdx.x] = 0.0;  g_sumsq[Cc + threadIdx.x] = 0.0;
    }
    __shared__ __align__(16) float sX[32 * C0];
    int tid = threadIdx.x;
    size_t row0 = (size_t)blockIdx.x * 32;
    size_t g = row0 / Ll;
    int l0 = (int)(row0 % Ll);                    // 32-aligned, rows stay in-graph
    const uint2* Xg = (const uint2*)(g_h0h + g * (size_t)Ll * C0);   // 16 uint2 per row

    // staging: aggregate 32 rows of 64ch from fp16 neighbors
    int cg = tid & 15;      // channel group of 4
    int rs = tid >> 4;      // 0..7 row subgroup
    #pragma unroll
    for (int rp = 0; rp < 32; rp += 8) {
        int node = l0 + rp + rs;
        float sn = g_selfnorm[node];
        uint2 hv = Xg[(size_t)node * 16 + cg];
        float2 a0 = __half22float2(*(const __half2*)&hv.x);
        float2 a1 = __half22float2(*(const __half2*)&hv.y);
        float4 acc = make_float4(sn * a0.x, sn * a0.y, sn * a1.x, sn * a1.y);
        int s = g_rowptr[node], e = g_rowptr[node + 1];
        for (int i = s; i < e; i++) {
            float nw = g_enorm[i];
            uint2 v = Xg[(size_t)g_col[i] * 16 + cg];
            float2 b0 = __half22float2(*(const __half2*)&v.x);
            float2 b1 = __half22float2(*(const __half2*)&v.y);
            acc.x += nw * b0.x; acc.y += nw * b0.y; acc.z += nw * b1.x; acc.w += nw * b1.y;
        }
        *(float4*)(sX + (rp + rs) * C0 + cg * 4) = acc;
    }
    __syncthreads();

    // GEMM K=64, 2-column register blocking
    int c = tid & 63, h = tid >> 6;
    ull accA[16], accB[16];
    #pragma unroll
    for (int r = 0; r < 16; r++) { accA[r] = 0ull; accB[r] = 0ull; }
    const float* sXh = sX + (h * 16) * C0;
    #pragma unroll 4
    for (int kq = 0; kq < C0 / 4; kq++) {
        ull wA0 = g_Wp1[(2 * kq)     * Cc + c];
        ull wA1 = g_Wp1[(2 * kq + 1) * Cc + c];
        ull wB0 = g_Wp1[(2 * kq)     * Cc + c + 64];
        ull wB1 = g_Wp1[(2 * kq + 1) * Cc + c + 64];
        #pragma unroll
        for (int r = 0; r < 16; r++) {
            ulonglong2 xv = *(const ulonglong2*)(sXh + r * C0 + 4 * kq);
            FFMA2(accA[r], xv.x, wA0);
            FFMA2(accA[r], xv.y, wA1);
            FFMA2(accB[r], xv.x, wB0);
            FFMA2(accB[r], xv.y, wB1);
        }
    }
    float bvA = bias[c], bvB = bias[c + 64];
    #pragma unroll
    for (int r = 0; r < 16; r++) {
        size_t row = row0 + h * 16 + r;
        float vA = __uint_as_float((unsigned)accA[r]) + __uint_as_float((unsigned)(accA[r] >> 32)) + bvA;
        float vB = __uint_as_float((unsigned)accB[r]) + __uint_as_float((unsigned)(accB[r] >> 32)) + bvB;
        g_a[row * Cc + c]      = vA;
        g_a[row * Cc + c + 64] = vB;
    }
}

// ---------------- GEMM (layers 2/3): Y[row,:] = act(X[row,:]) @ W[128,128] (+U) ----------------
template <bool ADD_U, bool HALF_OUT>
__device__ __forceinline__ void gemm_body128(
    const float* __restrict__ X, const ull* __restrict__ Wp,
    const float* __restrict__ U,
    const float* __restrict__ scale, const float* __restrict__ shift,
    float* __restrict__ Yf, __half* __restrict__ Yh)
{
    __shared__ __align__(16) float sX[32 * Cc];
    __shared__ float s_sc[Cc], s_sh[Cc];
    int tid = threadIdx.x;
    int c = tid & 63, h = tid >> 6;
    size_t row0 = (size_t)blockIdx.x * 32;

    s_sc[tid] = scale[tid]; s_sh[tid] = shift[tid];
    __syncthreads();

    const float4* Xv = (const float4*)(X + row0 * Cc);
    float4* sv = (float4*)sX;
    #pragma unroll
    for (int i = tid; i < 32 * Cc / 4; i += 128) {
        float4 v = Xv[i];
        int cc = (i * 4) % Cc;
        v.x = fmaxf(0.f, fmaf(v.x, s_sc[cc + 0], s_sh[cc + 0]));
        v.y = fmaxf(0.f, fmaf(v.y, s_sc[cc + 1], s_sh[cc + 1]));
        v.z = fmaxf(0.f, fmaf(v.z, s_sc[cc + 2], s_sh[cc + 2]));
        v.w = fmaxf(0.f, fmaf(v.w, s_sc[cc + 3], s_sh[cc + 3]));
        sv[i] = v;
    }
    __syncthreads();

    ull accA[16], accB[16];
    #pragma unroll
    for (int r = 0; r < 16; r++) { accA[r] = 0ull; accB[r] = 0ull; }

    const float* sXh = sX + (h * 16) * Cc;
    for (int kq = 0; kq < Cc / 4; kq++) {
        ull wA0 = Wp[(2 * kq)     * Cc + c];
        ull wA1 = Wp[(2 * kq + 1) * Cc + c];
        ull wB0 = Wp[(2 * kq)     * Cc + c + 64];
        ull wB1 = Wp[(2 * kq + 1) * Cc + c + 64];
        #pragma unroll
        for (int r = 0; r < 16; r++) {
            ulonglong2 xv = *(const ulonglong2*)(sXh + r * Cc + 4 * kq);
            FFMA2(accA[r], xv.x, wA0);
            FFMA2(accA[r], xv.y, wA1);
            FFMA2(accB[r], xv.x, wB0);
            FFMA2(accB[r], xv.y, wB1);
        }
    }

    #pragma unroll
    for (int r = 0; r < 16; r++) {
        size_t row = row0 + h * 16 + r;
        float vA = __uint_as_float((unsigned)accA[r]) + __uint_as_float((unsigned)(accA[r] >> 32));
        float vB = __uint_as_float((unsigned)accB[r]) + __uint_as_float((unsigned)(accB[r] >> 32));
        if (ADD_U) {
            size_t l = row % Ll;
            size_t b = row / ((size_t)Nn * Ll);
            const float* Up = U + (b * Ll + l) * Cc;
            vA += Up[c];
            vB += Up[c + 64];
        }
        if (HALF_OUT) {
            Yh[row * Cc + c]      = __float2half(vA);
            Yh[row * Cc + c + 64] = __float2half(vB);
        } else {
            Yf[row * Cc + c]      = vA;
            Yf[row * Cc + c + 64] = vB;
        }
    }
}

// U = relu(bn(amax)) @ W_up      (upper-half BN params: offset Cc)
__global__ __launch_bounds__(128) void gemmU_kernel(int wsel) {
    const ull* wp = ((wsel == 2) ? g_Wp2 : g_Wp3) + (Cc / 2) * Cc;
    gemm_body128<false, false>(g_amax, wp, nullptr, g_scale + Cc, g_shift + Cc, g_U, nullptr);
}
// hW = relu(bn(a)) @ W_low + U[b]  -> fp16 output for the gather
__global__ __launch_bounds__(128) void gemmM_kernel(int wsel) {
    const ull* wp = (wsel == 2) ? g_Wp2 : g_Wp3;
    gemm_body128<true, true>(g_a, wp, g_U, g_scale, g_shift, nullptr, g_hWh);
}

// ---------------- aggregation (fp16 payload, 128ch: layers 2/3) ----------------
__global__ __launch_bounds__(128) void agg2_kernel(const float* __restrict__ bias) {
    if (blockIdx.x == 0) {     // zero BN accumulators for this layer
        int t = threadIdx.x;
        g_sum[t] = 0.0;       g_sumsq[t] = 0.0;
        g_sum[Cc + t] = 0.0;  g_sumsq[Cc + t] = 0.0;
    }
    const int TPN = 32;
    int lane = threadIdx.x & 31;
    int nidx = threadIdx.x >> 5;
    size_t ng = (size_t)blockIdx.x * 4 + nidx;
    int node = (int)(ng % Ll);
    size_t g = ng / Ll;
    const uint2* Xg = (const uint2*)(g_hWh + g * Ll * Cc);

    float sn = g_selfnorm[node];
    uint2 hv = Xg[(size_t)node * TPN + lane];
    float2 f0 = __half22float2(*(const __half2*)&hv.x);
    float2 f1 = __half22float2(*(const __half2*)&hv.y);
    float4 acc = make_float4(sn * f0.x, sn * f0.y, sn * f1.x, sn * f1.y);

    int s = g_rowptr[node], e = g_rowptr[node + 1];
    for (int i = s; i < e; i++) {
        float nw = g_enorm[i];
        uint2 v = Xg[(size_t)g_col[i] * TPN + lane];
        float2 a0 = __half22float2(*(const __half2*)&v.x);
        float2 a1 = __half22float2(*(const __half2*)&v.y);
        acc.x += nw * a0.x; acc.y += nw * a0.y; acc.z += nw * a1.x; acc.w += nw * a1.y;
    }
    float4 bv = ((const float4*)bias)[lane];
    acc.x += bv.x; acc.y += bv.y; acc.z += bv.z; acc.w += bv.w;
    ((float4*)g_a)[ng * TPN + lane] = acc;
}

// ---------------- fused amax + BN stats: ONE pass over g_a ----------------
__global__ void amax_stats_kernel() {
    int c = threadIdx.x;
    float s_a = 0.f, ss_a = 0.f, s_m = 0.f, ss_m = 0.f;
    size_t base = (size_t)blockIdx.x * 8;
    #pragma unroll 1
    for (int j = 0; j < 8; j++) {
        size_t bl = base + j;                 // over B*L = 8192
        size_t b = bl / Ll, l = bl % Ll;
        const float* p = g_a + ((b * Nn) * Ll + l) * Cc + c;
        float m = -3.4e38f;
        #pragma unroll
        for (int n = 0; n < Nn; n++) {
            float v = p[(size_t)n * Ll * Cc];
            s_a += v; ss_a += v * v;
            m = fmaxf(m, v);
        }
        g_amax[bl * Cc + c] = m;
        s_m += m; ss_m += m * m;
    }
    atomicAdd(&g_sum[c],        (double)s_a);
    atomicAdd(&g_sumsq[c],      (double)ss_a);
    atomicAdd(&g_sum[Cc + c],   (double)s_m);
    atomicAdd(&g_sumsq[Cc + c], (double)ss_m);
}

__global__ void bn_kernel(const float* __restrict__ gamma, const float* __restrict__ beta) {
    int c = threadIdx.x;                       // 256
    double cnt = (c < Cc) ? (double)((size_t)Gg * Ll) : (double)((size_t)Bb * Ll);
    double mean = g_sum[c] / cnt;
    double var  = g_sumsq[c] / cnt - mean * mean;
    double inv  = 1.0 / sqrt(var + (double)EPSf);
    double sc   = (double)gamma[c] * inv;
    g_scale[c] = (float)sc;
    g_shift[c] = (float)((double)beta[c] - mean * sc);
}

// ---------------- final: BN+relu+concat+transpose to out [g, 256, l] ----------------
__global__ void final_kernel(float* __restrict__ out) {
    __shared__ float t[32][33];
    int g = blockIdx.z, c0 = blockIdx.y * 32, l0 = blockIdx.x * 32;
    int tx = threadIdx.x, ty = threadIdx.y;
    #pragma unroll
    for (int i = 0; i < 32; i += 8) {
        int l = l0 + ty + i;
        int c = c0 + tx;
        float v;
        if (c < Cc) v = g_a[((size_t)g * Ll + l) * Cc + c];
        else        v = g_amax[((size_t)(g / Nn) * Ll + l) * Cc + (c - Cc)];
        v = fmaxf(0.f, fmaf(v, g_scale[c], g_shift[c]));
        t[ty + i][tx] = v;
    }
    __syncthreads();
    #pragma unroll
    for (int i = 0; i < 32; i += 8) {
        int c = c0 + ty + i;
        int l = l0 + tx;
        out[((size_t)g * C2 + c) * Ll + l] = t[tx][ty + i];
    }
}

// ---------------- launch ----------------
extern "C" void kernel_launch(void* const* d_in, const int* in_sizes, int n_in,
                              void* d_out, int out_size) {
    const float* x  = (const float*)d_in[0];
    const void*  ei = d_in[1];   // int32 or int64, detected on device
    const float *W1 = (const float*)d_in[2],  *b1  = (const float*)d_in[3];
    const float *W2 = (const float*)d_in[4],  *b2  = (const float*)d_in[5];
    const float *W3 = (const float*)d_in[6],  *b3  = (const float*)d_in[7];
    const float *ga1 = (const float*)d_in[8],  *be1 = (const float*)d_in[9];
    const float *ga2 = (const float*)d_in[10], *be2 = (const float*)d_in[11];
    const float *ga3 = (const float*)d_in[12], *be3 = (const float*)d_in[13];
    float* out = (float*)d_out;

    const int rowsGL = Gg * Ll;   // 131072
    const int rowsBL = Bb * Ll;   // 8192

    // setup (launch idx 0..2)
    pack_weights<<<(288 * 128 + 255) / 256, 256>>>(W1, W2, W3);
    graph_build<<<1, 1024>>>((const unsigned int*)ei);
    transpose_x<<<dim3(Ll / 32, C0 / 32, Gg), dim3(32, 8)>>>(x);

    // ---- layer 1 (gemm1_fused = launch idx 3 -> ncu capture) ----
    gemm1_fused<<<rowsGL / 32, 128>>>(b1);        // gather + GEMM + zero stats
    amax_stats_kernel<<<rowsBL / 8, 128>>>();
    bn_kernel<<<1, C2>>>(ga1, be1);

    // ---- layer 2 ----
    gemmU_kernel<<<rowsBL / 32, 128>>>(2);
    gemmM_kernel<<<rowsGL / 32, 128>>>(2);
    agg2_kernel<<<rowsGL / 4, 128>>>(b2);         // also zeroes BN accumulators
    amax_stats_kernel<<<rowsBL / 8, 128>>>();
    bn_kernel<<<1, C2>>>(ga2, be2);

    // ---- layer 3 ----
    gemmU_kernel<<<rowsBL / 32, 128>>>(3);
    gemmM_kernel<<<rowsGL / 32, 128>>>(3);
    agg2_kernel<<<rowsGL / 4, 128>>>(b3);
    amax_stats_kernel<<<rowsBL / 8, 128>>>();
    bn_kernel<<<1, C2>>>(ga3, be3);

    // fused BN + relu + concat + transpose into output layout [b*n, 256, l]
    final_kernel<<<dim3(Ll / 32, C2 / 32, Gg), dim3(32, 8)>>>(out);
}

// round 12
// speedup vs baseline: 1.0523x; 1.0523x over previous
#include <cuda_runtime.h>
#include <cuda_fp16.h>
#include <math.h>

// Problem constants
#define Bb 4
#define Nn 16
#define Gg 64            // Bb*Nn
#define Ll 2048
#define Ee 32768
#define C0 64
#define Cc 128
#define C2 256
#define EPSf 1e-5

typedef unsigned long long ull;

// packed f32x2 FMA: d = a*b + d (elementwise on 2 packed floats)
#define FFMA2(d, a, b) asm("fma.rn.f32x2 %0, %1, %2, %3;" : "=l"(d) : "l"(a), "l"(b), "l"(d))

// ---------------- scratch (static device globals; no allocation) ----------------
__device__ __half g_h0h [Gg*Ll*C0];   // transposed x        [g,l,64] fp16
__device__ float  g_agg0[Gg*Ll*C0];   // A @ h0              [g,l,64]
__device__ __half g_hWh [Gg*Ll*Cc];   // GEMM out pre-agg    [g,l,128] fp16
__device__ float  g_a   [Gg*Ll*Cc];   // post-agg (+bias)    [g,l,128]
__device__ float  g_U   [Bb*Ll*Cc];   // act(amax) @ W_up    [b,l,128]
__device__ float  g_amax[Bb*Ll*Cc];   // max over n of a     [b,l,128]

__device__ ull g_Wp1[(C0/2)*Cc];     // packed W1  (32 kpairs x 128)
__device__ ull g_Wp2[(C2/2)*Cc];     // packed W2  (128 kpairs x 128; [0:64)=low, [64:128)=up)
__device__ ull g_Wp3[(C2/2)*Cc];     // packed W3

__device__ double g_sum[C2], g_sumsq[C2];
__device__ float  g_scale[C2], g_shift[C2];

__device__ int   g_rowptr[Ll+1];
__device__ int   g_col[Ee];
__device__ float g_enorm[Ee];
__device__ float g_selfnorm[Ll];

// ---------------- fused graph build: detect dtype + count + scan + fill ----------------
__global__ __launch_bounds__(1024) void graph_build(const unsigned int* __restrict__ w) {
    __shared__ int   s_any;
    __shared__ int   s_cnt[Ll];
    __shared__ int   s_base[Ll];
    __shared__ float s_dinv[Ll];
    __shared__ int   s_wsum[32];
    int tid = threadIdx.x;

    if (tid == 0) s_any = 0;
    s_cnt[tid] = 0; s_cnt[tid + 1024] = 0;
    __syncthreads();

    // dtype detect: int64 layout with values<2048 -> all odd u32 words zero
    int any = 0;
    for (int i = 2 * tid + 1; i < 16384; i += 2048)
        if (w[i] != 0u) any = 1;
    if (any) s_any = 1;
    __syncthreads();
    const int is64 = (s_any == 0);

    // count in-degree (smem atomics)
    for (int e = tid; e < Ee; e += 1024) {
        int d = (is64 ? (int)w[2 * (Ee + e)] : (int)w[Ee + e]) & (Ll - 1);
        atomicAdd(&s_cnt[d], 1);
    }
    __syncthreads();

    // exclusive scan over 2048 counts (2 per thread)
    int n0 = 2 * tid, n1 = 2 * tid + 1;
    int v0 = s_cnt[n0], v1 = s_cnt[n1];
    int s = v0 + v1;
    int lane = tid & 31, wid = tid >> 5;
    int own = s;
    #pragma unroll
    for (int off = 1; off < 32; off <<= 1) {
        int t = __shfl_up_sync(0xffffffffu, s, off);
        if (lane >= off) s += t;
    }
    if (lane == 31) s_wsum[wid] = s;
    __syncthreads();
    if (wid == 0) {
        int t = s_wsum[lane];
        int o = t;
        #pragma unroll
        for (int off = 1; off < 32; off <<= 1) {
            int u = __shfl_up_sync(0xffffffffu, t, off);
            if (lane >= off) t += u;
        }
        s_wsum[lane] = t - o;   // exclusive warp offsets
    }
    __syncthreads();
    int run = s_wsum[wid] + s - own;    // exclusive prefix for node n0

    g_rowptr[n0] = run;  s_base[n0] = run;
    float deg0 = (float)v0 + 2.0f;
    s_dinv[n0] = rsqrtf(deg0); g_selfnorm[n0] = 2.0f / deg0;
    int run1 = run + v0;
    g_rowptr[n1] = run1; s_base[n1] = run1;
    float deg1 = (float)v1 + 2.0f;
    s_dinv[n1] = rsqrtf(deg1); g_selfnorm[n1] = 2.0f / deg1;
    if (tid == 1023) g_rowptr[Ll] = run1 + v1;
    s_cnt[n0] = 0; s_cnt[n1] = 0;   // reuse as fill cursors
    __syncthreads();

    // fill CSR
    for (int e = tid; e < Ee; e += 1024) {
        int sN = (is64 ? (int)w[2 * e]        : (int)w[e])        & (Ll - 1);
        int d  = (is64 ? (int)w[2 * (Ee + e)] : (int)w[Ee + e])   & (Ll - 1);
        int pos = s_base[d] + atomicAdd(&s_cnt[d], 1);
        g_col[pos] = sN;
        g_enorm[pos] = s_dinv[sN] * s_dinv[d];
    }
}

// ---------------- pack weights into u64 k-pairs ----------------
__global__ void pack_weights(const float* __restrict__ W1,
                             const float* __restrict__ W2,
                             const float* __restrict__ W3) {
    int flat = blockIdx.x * blockDim.x + threadIdx.x;   // 0 .. 288*128-1
    const int N1 = (C0/2) * Cc;          // 4096
    const int N2 = (C2/2) * Cc;          // 16384
    if (flat < N1) {
        int kp = flat / Cc, c = flat % Cc;
        unsigned lo = __float_as_uint(W1[(2*kp)   * Cc + c]);
        unsigned hi = __float_as_uint(W1[(2*kp+1) * Cc + c]);
        g_Wp1[flat] = (ull)lo | ((ull)hi << 32);
    } else if (flat < N1 + N2) {
        int f = flat - N1;
        int kp = f / Cc, c = f % Cc;
        unsigned lo = __float_as_uint(W2[(2*kp)   * Cc + c]);
        unsigned hi = __float_as_uint(W2[(2*kp+1) * Cc + c]);
        g_Wp2[f] = (ull)lo | ((ull)hi << 32);
    } else if (flat < N1 + 2*N2) {
        int f = flat - N1 - N2;
        int kp = f / Cc, c = f % Cc;
        unsigned lo = __float_as_uint(W3[(2*kp)   * Cc + c]);
        unsigned hi = __float_as_uint(W3[(2*kp+1) * Cc + c]);
        g_Wp3[f] = (ull)lo | ((ull)hi << 32);
    }
}

// ---------------- transpose x [b,n,c,l] -> g_h0h [g,l,c] fp16 ----------------
__global__ void transpose_x(const float* __restrict__ x) {
    __shared__ float t[32][33];
    int g = blockIdx.z, c0 = blockIdx.y * 32, l0 = blockIdx.x * 32;
    int tx = threadIdx.x, ty = threadIdx.y;
    #pragma unroll
    for (int i = 0; i < 32; i += 8) {
        int c = c0 + ty + i, l = l0 + tx;
        t[ty + i][tx] = x[((size_t)(g * C0 + c)) * Ll + l];
    }
    __syncthreads();
    #pragma unroll
    for (int i = 0; i < 32; i += 8) {
        int l = l0 + ty + i, c = c0 + tx;
        g_h0h[((size_t)g * Ll + l) * C0 + c] = __float2half(t[tx][ty + i]);
    }
}

// ---------------- aggregation layer 1 (fp16 payload, 64ch) ----------------
// 16 threads per node (uint2 = 4ch each), 8 nodes/block, high occupancy.
__global__ __launch_bounds__(128) void agg1_kernel() {
    int lane = threadIdx.x & 15;
    int nidx = threadIdx.x >> 4;
    size_t ng = (size_t)blockIdx.x * 8 + nidx;       // over G*L
    int node = (int)(ng % Ll);
    size_t g = ng / Ll;
    const uint2* Xg = (const uint2*)(g_h0h + g * (size_t)Ll * C0);   // 16 uint2 per row

    float sn = g_selfnorm[node];
    uint2 hv = Xg[(size_t)node * 16 + lane];
    float2 f0 = __half22float2(*(const __half2*)&hv.x);
    float2 f1 = __half22float2(*(const __half2*)&hv.y);
    float4 acc = make_float4(sn * f0.x, sn * f0.y, sn * f1.x, sn * f1.y);

    int s = g_rowptr[node], e = g_rowptr[node + 1];
    for (int i = s; i < e; i++) {
        float nw = g_enorm[i];
        uint2 v = Xg[(size_t)g_col[i] * 16 + lane];
        float2 a0 = __half22float2(*(const __half2*)&v.x);
        float2 a1 = __half22float2(*(const __half2*)&v.y);
        acc.x += nw * a0.x; acc.y += nw * a0.y; acc.z += nw * a1.x; acc.w += nw * a1.y;
    }
    ((float4*)g_agg0)[ng * 16 + lane] = acc;
}

// ---------------- GEMM layer 1: a = agg0 @ W1 + b1  (K=64) ----------------
// 256 threads: c = tid&63 -> cols {c, c+64}; q = tid>>6 -> rows [q*8, q*8+8)
__global__ __launch_bounds__(256) void gemm1_kernel(const float* __restrict__ bias) {
    if (blockIdx.x == 0 && threadIdx.x < 128) {   // zero BN stat accumulators
        g_sum[threadIdx.x] = 0.0;       g_sumsq[threadIdx.x] = 0.0;
        g_sum[Cc + threadIdx.x] = 0.0;  g_sumsq[Cc + threadIdx.x] = 0.0;
    }
    __shared__ __align__(16) float sX[32 * C0];
    int tid = threadIdx.x;
    int c = tid & 63, q = tid >> 6;
    size_t row0 = (size_t)blockIdx.x * 32;

    const float4* Xv = (const float4*)(g_agg0 + row0 * C0);
    float4* sv = (float4*)sX;
    #pragma unroll
    for (int i = tid; i < 32 * C0 / 4; i += 256) sv[i] = Xv[i];
    __syncthreads();

    ull accA[8], accB[8];
    #pragma unroll
    for (int r = 0; r < 8; r++) { accA[r] = 0ull; accB[r] = 0ull; }

    const float* sXq = sX + (q * 8) * C0;
    #pragma unroll 4
    for (int kq = 0; kq < C0 / 4; kq++) {
        ull wA0 = g_Wp1[(2 * kq)     * Cc + c];
        ull wA1 = g_Wp1[(2 * kq + 1) * Cc + c];
        ull wB0 = g_Wp1[(2 * kq)     * Cc + c + 64];
        ull wB1 = g_Wp1[(2 * kq + 1) * Cc + c + 64];
        #pragma unroll
        for (int r = 0; r < 8; r++) {
            ulonglong2 xv = *(const ulonglong2*)(sXq + r * C0 + 4 * kq);
            FFMA2(accA[r], xv.x, wA0);
            FFMA2(accA[r], xv.y, wA1);
            FFMA2(accB[r], xv.x, wB0);
            FFMA2(accB[r], xv.y, wB1);
        }
    }
    float bvA = bias[c], bvB = bias[c + 64];
    #pragma unroll
    for (int r = 0; r < 8; r++) {
        size_t row = row0 + q * 8 + r;
        float vA = __uint_as_float((unsigned)accA[r]) + __uint_as_float((unsigned)(accA[r] >> 32)) + bvA;
        float vB = __uint_as_float((unsigned)accB[r]) + __uint_as_float((unsigned)(accB[r] >> 32)) + bvB;
        g_a[row * Cc + c]      = vA;
        g_a[row * Cc + c + 64] = vB;
    }
}

// ---------------- GEMM (layers 2/3): Y[row,:] = act(X[row,:]) @ W[128,128] (+U) ----------------
// 256 threads: c = tid&63 -> cols {c, c+64}; q = tid>>6 -> rows [q*8, q*8+8)
template <bool ADD_U, bool HALF_OUT>
__device__ __forceinline__ void gemm_body128(
    const float* __restrict__ X, const ull* __restrict__ Wp,
    const float* __restrict__ U,
    const float* __restrict__ scale, const float* __restrict__ shift,
    float* __restrict__ Yf, __half* __restrict__ Yh)
{
    __shared__ __align__(16) float sX[32 * Cc];
    __shared__ float s_sc[Cc], s_sh[Cc];
    int tid = threadIdx.x;
    int c = tid & 63, q = tid >> 6;
    size_t row0 = (size_t)blockIdx.x * 32;

    if (tid < Cc) { s_sc[tid] = scale[tid]; s_sh[tid] = shift[tid]; }
    __syncthreads();

    const float4* Xv = (const float4*)(X + row0 * Cc);
    float4* sv = (float4*)sX;
    #pragma unroll
    for (int i = tid; i < 32 * Cc / 4; i += 256) {
        float4 v = Xv[i];
        int cc = (i * 4) % Cc;
        v.x = fmaxf(0.f, fmaf(v.x, s_sc[cc + 0], s_sh[cc + 0]));
        v.y = fmaxf(0.f, fmaf(v.y, s_sc[cc + 1], s_sh[cc + 1]));
        v.z = fmaxf(0.f, fmaf(v.z, s_sc[cc + 2], s_sh[cc + 2]));
        v.w = fmaxf(0.f, fmaf(v.w, s_sc[cc + 3], s_sh[cc + 3]));
        sv[i] = v;
    }
    __syncthreads();

    ull accA[8], accB[8];
    #pragma unroll
    for (int r = 0; r < 8; r++) { accA[r] = 0ull; accB[r] = 0ull; }

    const float* sXq = sX + (q * 8) * Cc;
    #pragma unroll 4
    for (int kq = 0; kq < Cc / 4; kq++) {
        ull wA0 = Wp[(2 * kq)     * Cc + c];
        ull wA1 = Wp[(2 * kq + 1) * Cc + c];
        ull wB0 = Wp[(2 * kq)     * Cc + c + 64];
        ull wB1 = Wp[(2 * kq + 1) * Cc + c + 64];
        #pragma unroll
        for (int r = 0; r < 8; r++) {
            ulonglong2 xv = *(const ulonglong2*)(sXq + r * Cc + 4 * kq);
            FFMA2(accA[r], xv.x, wA0);
            FFMA2(accA[r], xv.y, wA1);
            FFMA2(accB[r], xv.x, wB0);
            FFMA2(accB[r], xv.y, wB1);
        }
    }

    #pragma unroll
    for (int r = 0; r < 8; r++) {
        size_t row = row0 + q * 8 + r;
        float vA = __uint_as_float((unsigned)accA[r]) + __uint_as_float((unsigned)(accA[r] >> 32));
        float vB = __uint_as_float((unsigned)accB[r]) + __uint_as_float((unsigned)(accB[r] >> 32));
        if (ADD_U) {
            size_t l = row % Ll;
            size_t b = row / ((size_t)Nn * Ll);
            const float* Up = U + (b * Ll + l) * Cc;
            vA += Up[c];
            vB += Up[c + 64];
        }
        if (HALF_OUT) {
            Yh[row * Cc + c]      = __float2half(vA);
            Yh[row * Cc + c + 64] = __float2half(vB);
        } else {
            Yf[row * Cc + c]      = vA;
            Yf[row * Cc + c + 64] = vB;
        }
    }
}

// U = relu(bn(amax)) @ W_up      (upper-half BN params: offset Cc)
__global__ __launch_bounds__(256) void gemmU_kernel(int wsel) {
    const ull* wp = ((wsel == 2) ? g_Wp2 : g_Wp3) + (Cc / 2) * Cc;
    gemm_body128<false, false>(g_amax, wp, nullptr, g_scale + Cc, g_shift + Cc, g_U, nullptr);
}
// hW = relu(bn(a)) @ W_low + U[b]  -> fp16 output for the gather
__global__ __launch_bounds__(256) void gemmM_kernel(int wsel) {
    const ull* wp = (wsel == 2) ? g_Wp2 : g_Wp3;
    gemm_body128<true, true>(g_a, wp, g_U, g_scale, g_shift, nullptr, g_hWh);
}

// ---------------- aggregation (fp16 payload, 128ch: layers 2/3) ----------------
__global__ __launch_bounds__(128) void agg2_kernel(const float* __restrict__ bias) {
    if (blockIdx.x == 0) {     // zero BN accumulators for this layer
        int t = threadIdx.x;
        g_sum[t] = 0.0;       g_sumsq[t] = 0.0;
        g_sum[Cc + t] = 0.0;  g_sumsq[Cc + t] = 0.0;
    }
    const int TPN = 32;
    int lane = threadIdx.x & 31;
    int nidx = threadIdx.x >> 5;
    size_t ng = (size_t)blockIdx.x * 4 + nidx;
    int node = (int)(ng % Ll);
    size_t g = ng / Ll;
    const uint2* Xg = (const uint2*)(g_hWh + g * Ll * Cc);

    float sn = g_selfnorm[node];
    uint2 hv = Xg[(size_t)node * TPN + lane];
    float2 f0 = __half22float2(*(const __half2*)&hv.x);
    float2 f1 = __half22float2(*(const __half2*)&hv.y);
    float4 acc = make_float4(sn * f0.x, sn * f0.y, sn * f1.x, sn * f1.y);

    int s = g_rowptr[node], e = g_rowptr[node + 1];
    for (int i = s; i < e; i++) {
        float nw = g_enorm[i];
        uint2 v = Xg[(size_t)g_col[i] * TPN + lane];
        float2 a0 = __half22float2(*(const __half2*)&v.x);
        float2 a1 = __half22float2(*(const __half2*)&v.y);
        acc.x += nw * a0.x; acc.y += nw * a0.y; acc.z += nw * a1.x; acc.w += nw * a1.y;
    }
    float4 bv = ((const float4*)bias)[lane];
    acc.x += bv.x; acc.y += bv.y; acc.z += bv.z; acc.w += bv.w;
    ((float4*)g_a)[ng * TPN + lane] = acc;
}

// ---------------- fused amax + BN stats: ONE pass over g_a ----------------
__global__ void amax_stats_kernel() {
    int c = threadIdx.x;
    float s_a = 0.f, ss_a = 0.f, s_m = 0.f, ss_m = 0.f;
    size_t base = (size_t)blockIdx.x * 8;
    #pragma unroll 1
    for (int j = 0; j < 8; j++) {
        size_t bl = base + j;                 // over B*L = 8192
        size_t b = bl / Ll, l = bl % Ll;
        const float* p = g_a + ((b * Nn) * Ll + l) * Cc + c;
        float m = -3.4e38f;
        #pragma unroll
        for (int n = 0; n < Nn; n++) {
            float v = p[(size_t)n * Ll * Cc];
            s_a += v; ss_a += v * v;
            m = fmaxf(m, v);
        }
        g_amax[bl * Cc + c] = m;
        s_m += m; ss_m += m * m;
    }
    atomicAdd(&g_sum[c],        (double)s_a);
    atomicAdd(&g_sumsq[c],      (double)ss_a);
    atomicAdd(&g_sum[Cc + c],   (double)s_m);
    atomicAdd(&g_sumsq[Cc + c], (double)ss_m);
}

__global__ void bn_kernel(const float* __restrict__ gamma, const float* __restrict__ beta) {
    int c = threadIdx.x;                       // 256
    double cnt = (c < Cc) ? (double)((size_t)Gg * Ll) : (double)((size_t)Bb * Ll);
    double mean = g_sum[c] / cnt;
    double var  = g_sumsq[c] / cnt - mean * mean;
    double inv  = 1.0 / sqrt(var + (double)EPSf);
    double sc   = (double)gamma[c] * inv;
    g_scale[c] = (float)sc;
    g_shift[c] = (float)((double)beta[c] - mean * sc);
}

// ---------------- final: BN+relu+concat+transpose to out [g, 256, l] ----------------
__global__ void final_kernel(float* __restrict__ out) {
    __shared__ float t[32][33];
    int g = blockIdx.z, c0 = blockIdx.y * 32, l0 = blockIdx.x * 32;
    int tx = threadIdx.x, ty = threadIdx.y;
    #pragma unroll
    for (int i = 0; i < 32; i += 8) {
        int l = l0 + ty + i;
        int c = c0 + tx;
        float v;
        if (c < Cc) v = g_a[((size_t)g * Ll + l) * Cc + c];
        else        v = g_amax[((size_t)(g / Nn) * Ll + l) * Cc + (c - Cc)];
        v = fmaxf(0.f, fmaf(v, g_scale[c], g_shift[c]));
        t[ty + i][tx] = v;
    }
    __syncthreads();
    #pragma unroll
    for (int i = 0; i < 32; i += 8) {
        int c = c0 + ty + i;
        int l = l0 + tx;
        out[((size_t)g * C2 + c) * Ll + l] = t[tx][ty + i];
    }
}

// ---------------- launch ----------------
extern "C" void kernel_launch(void* const* d_in, const int* in_sizes, int n_in,
                              void* d_out, int out_size) {
    const float* x  = (const float*)d_in[0];
    const void*  ei = d_in[1];   // int32 or int64, detected on device
    const float *W1 = (const float*)d_in[2],  *b1  = (const float*)d_in[3];
    const float *W2 = (const float*)d_in[4],  *b2  = (const float*)d_in[5];
    const float *W3 = (const float*)d_in[6],  *b3  = (const float*)d_in[7];
    const float *ga1 = (const float*)d_in[8],  *be1 = (const float*)d_in[9];
    const float *ga2 = (const float*)d_in[10], *be2 = (const float*)d_in[11];
    const float *ga3 = (const float*)d_in[12], *be3 = (const float*)d_in[13];
    float* out = (float*)d_out;

    const int rowsGL = Gg * Ll;   // 131072
    const int rowsBL = Bb * Ll;   // 8192

    // setup (launch idx 0..2)
    pack_weights<<<(288 * 128 + 255) / 256, 256>>>(W1, W2, W3);
    graph_build<<<1, 1024>>>((const unsigned int*)ei);
    transpose_x<<<dim3(Ll / 32, C0 / 32, Gg), dim3(32, 8)>>>(x);

    // ---- layer 1 (agg1 = launch idx 3 -> ncu capture) ----
    agg1_kernel<<<rowsGL / 8, 128>>>();
    gemm1_kernel<<<rowsGL / 32, 256>>>(b1);       // also zeroes BN accumulators
    amax_stats_kernel<<<rowsBL / 8, 128>>>();
    bn_kernel<<<1, C2>>>(ga1, be1);

    // ---- layer 2 ----
    gemmU_kernel<<<rowsBL / 32, 256>>>(2);
    gemmM_kernel<<<rowsGL / 32, 256>>>(2);
    agg2_kernel<<<rowsGL / 4, 128>>>(b2);         // also zeroes BN accumulators
    amax_stats_kernel<<<rowsBL / 8, 128>>>();
    bn_kernel<<<1, C2>>>(ga2, be2);

    // ---- layer 3 ----
    gemmU_kernel<<<rowsBL / 32, 256>>>(3);
    gemmM_kernel<<<rowsGL / 32, 256>>>(3);
    agg2_kernel<<<rowsGL / 4, 128>>>(b3);
    amax_stats_kernel<<<rowsBL / 8, 128>>>();
    bn_kernel<<<1, C2>>>(ga3, be3);

    // fused BN + relu + concat + transpose into output layout [b*n, 256, l]
    final_kernel<<<dim3(Ll / 32, C2 / 32, Gg), dim3(32, 8)>>>(out);
}

// round 13
// speedup vs baseline: 1.0524x; 1.0001x over previous
#include <cuda_runtime.h>
#include <cuda_fp16.h>
#include <math.h>

// Problem constants
#define Bb 4
#define Nn 16
#define Gg 64            // Bb*Nn
#define Ll 2048
#define Ee 32768
#define C0 64
#define Cc 128
#define C2 256
#define EPSf 1e-5

typedef unsigned long long ull;

// packed f32x2 FMA: d = a*b + d (elementwise on 2 packed floats)
#define FFMA2(d, a, b) asm("fma.rn.f32x2 %0, %1, %2, %3;" : "=l"(d) : "l"(a), "l"(b), "l"(d))

__device__ __forceinline__ ull dupu(unsigned x) {
    ull r; asm("mov.b64 %0, {%1, %1};" : "=l"(r) : "r"(x)); return r;
}
__device__ __forceinline__ ull dupf(float x) {
    ull r; asm("mov.b64 %0, {%1, %1};" : "=l"(r) : "f"(x)); return r;
}

// ---------------- scratch (static device globals; no allocation) ----------------
__device__ __half g_h0h [Gg*Ll*C0];   // transposed x        [g,l,64] fp16
__device__ float  g_agg0[Gg*Ll*C0];   // A @ h0              [g,l,64]
__device__ __half g_hWh [Gg*Ll*Cc];   // GEMM out pre-agg    [g,l,128] fp16
__device__ float  g_a   [Gg*Ll*Cc];   // post-agg (+bias)    [g,l,128]
__device__ float  g_U   [Bb*Ll*Cc];   // act(amax) @ W_up    [b,l,128]
__device__ float  g_amax[Bb*Ll*Cc];   // max over n of a     [b,l,128]

__device__ ull g_Wp1[(C0/2)*Cc];     // packed W1  (32 kpairs x 128)
__device__ ull g_Wp2[(C2/2)*Cc];     // packed W2  (128 kpairs x 128; [0:64)=low, [64:128)=up)
__device__ ull g_Wp3[(C2/2)*Cc];     // packed W3

__device__ double g_sum[C2], g_sumsq[C2];
__device__ float  g_scale[C2], g_shift[C2];

__device__ int   g_rowptr[Ll+1];
__device__ uint2 g_edge[Ee];         // {src_col, enorm_bits}
__device__ float g_selfnorm[Ll];

// ---------------- fused graph build: detect dtype + count + scan + fill ----------------
__global__ __launch_bounds__(1024) void graph_build(const unsigned int* __restrict__ w) {
    __shared__ int   s_any;
    __shared__ int   s_cnt[Ll];
    __shared__ int   s_base[Ll];
    __shared__ float s_dinv[Ll];
    __shared__ int   s_wsum[32];
    int tid = threadIdx.x;

    if (tid == 0) s_any = 0;
    s_cnt[tid] = 0; s_cnt[tid + 1024] = 0;
    __syncthreads();

    // dtype detect: int64 layout with values<2048 -> all odd u32 words zero
    int any = 0;
    for (int i = 2 * tid + 1; i < 16384; i += 2048)
        if (w[i] != 0u) any = 1;
    if (any) s_any = 1;
    __syncthreads();
    const int is64 = (s_any == 0);

    // count in-degree (smem atomics)
    for (int e = tid; e < Ee; e += 1024) {
        int d = (is64 ? (int)w[2 * (Ee + e)] : (int)w[Ee + e]) & (Ll - 1);
        atomicAdd(&s_cnt[d], 1);
    }
    __syncthreads();

    // exclusive scan over 2048 counts (2 per thread)
    int n0 = 2 * tid, n1 = 2 * tid + 1;
    int v0 = s_cnt[n0], v1 = s_cnt[n1];
    int s = v0 + v1;
    int lane = tid & 31, wid = tid >> 5;
    int own = s;
    #pragma unroll
    for (int off = 1; off < 32; off <<= 1) {
        int t = __shfl_up_sync(0xffffffffu, s, off);
        if (lane >= off) s += t;
    }
    if (lane == 31) s_wsum[wid] = s;
    __syncthreads();
    if (wid == 0) {
        int t = s_wsum[lane];
        int o = t;
        #pragma unroll
        for (int off = 1; off < 32; off <<= 1) {
            int u = __shfl_up_sync(0xffffffffu, t, off);
            if (lane >= off) t += u;
        }
        s_wsum[lane] = t - o;   // exclusive warp offsets
    }
    __syncthreads();
    int run = s_wsum[wid] + s - own;    // exclusive prefix for node n0

    g_rowptr[n0] = run;  s_base[n0] = run;
    float deg0 = (float)v0 + 2.0f;
    s_dinv[n0] = rsqrtf(deg0); g_selfnorm[n0] = 2.0f / deg0;
    int run1 = run + v0;
    g_rowptr[n1] = run1; s_base[n1] = run1;
    float deg1 = (float)v1 + 2.0f;
    s_dinv[n1] = rsqrtf(deg1); g_selfnorm[n1] = 2.0f / deg1;
    if (tid == 1023) g_rowptr[Ll] = run1 + v1;
    s_cnt[n0] = 0; s_cnt[n1] = 0;   // reuse as fill cursors
    __syncthreads();

    // fill CSR (packed edge: src col + norm)
    for (int e = tid; e < Ee; e += 1024) {
        int sN = (is64 ? (int)w[2 * e]        : (int)w[e])        & (Ll - 1);
        int d  = (is64 ? (int)w[2 * (Ee + e)] : (int)w[Ee + e])   & (Ll - 1);
        int pos = s_base[d] + atomicAdd(&s_cnt[d], 1);
        g_edge[pos] = make_uint2((unsigned)sN, __float_as_uint(s_dinv[sN] * s_dinv[d]));
    }
}

// ---------------- pack weights into u64 k-pairs ----------------
__global__ void pack_weights(const float* __restrict__ W1,
                             const float* __restrict__ W2,
                             const float* __restrict__ W3) {
    int flat = blockIdx.x * blockDim.x + threadIdx.x;   // 0 .. 288*128-1
    const int N1 = (C0/2) * Cc;          // 4096
    const int N2 = (C2/2) * Cc;          // 16384
    if (flat < N1) {
        int kp = flat / Cc, c = flat % Cc;
        unsigned lo = __float_as_uint(W1[(2*kp)   * Cc + c]);
        unsigned hi = __float_as_uint(W1[(2*kp+1) * Cc + c]);
        g_Wp1[flat] = (ull)lo | ((ull)hi << 32);
    } else if (flat < N1 + N2) {
        int f = flat - N1;
        int kp = f / Cc, c = f % Cc;
        unsigned lo = __float_as_uint(W2[(2*kp)   * Cc + c]);
        unsigned hi = __float_as_uint(W2[(2*kp+1) * Cc + c]);
        g_Wp2[f] = (ull)lo | ((ull)hi << 32);
    } else if (flat < N1 + 2*N2) {
        int f = flat - N1 - N2;
        int kp = f / Cc, c = f % Cc;
        unsigned lo = __float_as_uint(W3[(2*kp)   * Cc + c]);
        unsigned hi = __float_as_uint(W3[(2*kp+1) * Cc + c]);
        g_Wp3[f] = (ull)lo | ((ull)hi << 32);
    }
}

// ---------------- transpose x [b,n,c,l] -> g_h0h [g,l,c] fp16 ----------------
__global__ void transpose_x(const float* __restrict__ x) {
    __shared__ float t[32][33];
    int g = blockIdx.z, c0 = blockIdx.y * 32, l0 = blockIdx.x * 32;
    int tx = threadIdx.x, ty = threadIdx.y;
    #pragma unroll
    for (int i = 0; i < 32; i += 8) {
        int c = c0 + ty + i, l = l0 + tx;
        t[ty + i][tx] = x[((size_t)(g * C0 + c)) * Ll + l];
    }
    __syncthreads();
    #pragma unroll
    for (int i = 0; i < 32; i += 8) {
        int l = l0 + ty + i, c = c0 + tx;
        g_h0h[((size_t)g * Ll + l) * C0 + c] = __float2half(t[tx][ty + i]);
    }
}

// ---------------- aggregation layer 1 (fp16 uint4 payload, 64ch, 8 lanes/node) ----------------
__global__ __launch_bounds__(128) void agg1_kernel() {
    int lane = threadIdx.x & 7;
    int nidx = threadIdx.x >> 3;                      // 16 nodes/block
    size_t ng = (size_t)blockIdx.x * 16 + nidx;       // over G*L
    int node = (int)(ng & (Ll - 1));
    size_t g = ng / Ll;
    const uint4* Xg = (const uint4*)(g_h0h + g * (size_t)Ll * C0);   // 8 uint4 per row

    ull acc[4] = {0ull, 0ull, 0ull, 0ull};
    {
        ull sn2 = dupf(g_selfnorm[node]);
        uint4 hv = Xg[(size_t)node * 8 + lane];
        float2 f0 = __half22float2(*(const __half2*)&hv.x); FFMA2(acc[0], *(ull*)&f0, sn2);
        float2 f1 = __half22float2(*(const __half2*)&hv.y); FFMA2(acc[1], *(ull*)&f1, sn2);
        float2 f2 = __half22float2(*(const __half2*)&hv.z); FFMA2(acc[2], *(ull*)&f2, sn2);
        float2 f3 = __half22float2(*(const __half2*)&hv.w); FFMA2(acc[3], *(ull*)&f3, sn2);
    }
    int s = g_rowptr[node], e = g_rowptr[node + 1];
    for (int i = s; i < e; i++) {
        uint2 ed = g_edge[i];
        ull nw2 = dupu(ed.y);
        uint4 v = Xg[(size_t)ed.x * 8 + lane];
        float2 a0 = __half22float2(*(const __half2*)&v.x); FFMA2(acc[0], *(ull*)&a0, nw2);
        float2 a1 = __half22float2(*(const __half2*)&v.y); FFMA2(acc[1], *(ull*)&a1, nw2);
        float2 a2 = __half22float2(*(const __half2*)&v.z); FFMA2(acc[2], *(ull*)&a2, nw2);
        float2 a3 = __half22float2(*(const __half2*)&v.w); FFMA2(acc[3], *(ull*)&a3, nw2);
    }
    float2 p0 = *(float2*)&acc[0], p1 = *(float2*)&acc[1];
    float2 p2 = *(float2*)&acc[2], p3 = *(float2*)&acc[3];
    ((float4*)g_agg0)[ng * 16 + lane * 2]     = make_float4(p0.x, p0.y, p1.x, p1.y);
    ((float4*)g_agg0)[ng * 16 + lane * 2 + 1] = make_float4(p2.x, p2.y, p3.x, p3.y);
}

// ---------------- aggregation layers 2/3 (fp16 uint4 payload, 128ch, 16 lanes/node) ----------------
__global__ __launch_bounds__(128) void agg2_kernel(const float* __restrict__ bias) {
    if (blockIdx.x == 0) {     // zero BN accumulators for this layer
        int t = threadIdx.x;
        g_sum[t] = 0.0;       g_sumsq[t] = 0.0;
        g_sum[Cc + t] = 0.0;  g_sumsq[Cc + t] = 0.0;
    }
    int lane = threadIdx.x & 15;
    int nidx = threadIdx.x >> 4;                      // 8 nodes/block
    size_t ng = (size_t)blockIdx.x * 8 + nidx;        // over G*L
    int node = (int)(ng & (Ll - 1));
    size_t g = ng / Ll;
    const uint4* Xg = (const uint4*)(g_hWh + g * (size_t)Ll * Cc);   // 16 uint4 per row

    ull acc[4] = {0ull, 0ull, 0ull, 0ull};
    {
        ull sn2 = dupf(g_selfnorm[node]);
        uint4 hv = Xg[(size_t)node * 16 + lane];
        float2 f0 = __half22float2(*(const __half2*)&hv.x); FFMA2(acc[0], *(ull*)&f0, sn2);
        float2 f1 = __half22float2(*(const __half2*)&hv.y); FFMA2(acc[1], *(ull*)&f1, sn2);
        float2 f2 = __half22float2(*(const __half2*)&hv.z); FFMA2(acc[2], *(ull*)&f2, sn2);
        float2 f3 = __half22float2(*(const __half2*)&hv.w); FFMA2(acc[3], *(ull*)&f3, sn2);
    }
    int s = g_rowptr[node], e = g_rowptr[node + 1];
    for (int i = s; i < e; i++) {
        uint2 ed = g_edge[i];
        ull nw2 = dupu(ed.y);
        uint4 v = Xg[(size_t)ed.x * 16 + lane];
        float2 a0 = __half22float2(*(const __half2*)&v.x); FFMA2(acc[0], *(ull*)&a0, nw2);
        float2 a1 = __half22float2(*(const __half2*)&v.y); FFMA2(acc[1], *(ull*)&a1, nw2);
        float2 a2 = __half22float2(*(const __half2*)&v.z); FFMA2(acc[2], *(ull*)&a2, nw2);
        float2 a3 = __half22float2(*(const __half2*)&v.w); FFMA2(acc[3], *(ull*)&a3, nw2);
    }
    float2 p0 = *(float2*)&acc[0], p1 = *(float2*)&acc[1];
    float2 p2 = *(float2*)&acc[2], p3 = *(float2*)&acc[3];
    float4 b0 = ((const float4*)bias)[lane * 2];
    float4 b1 = ((const float4*)bias)[lane * 2 + 1];
    ((float4*)g_a)[ng * 32 + lane * 2]     = make_float4(p0.x + b0.x, p0.y + b0.y, p1.x + b0.z, p1.y + b0.w);
    ((float4*)g_a)[ng * 32 + lane * 2 + 1] = make_float4(p2.x + b1.x, p2.y + b1.y, p3.x + b1.z, p3.y + b1.w);
}

// ---------------- GEMM layer 1: a = agg0 @ W1 + b1  (K=64, 64 rows/block) ----------------
__global__ __launch_bounds__(256) void gemm1_kernel(const float* __restrict__ bias) {
    if (blockIdx.x == 0 && threadIdx.x < 128) {   // zero BN stat accumulators
        g_sum[threadIdx.x] = 0.0;       g_sumsq[threadIdx.x] = 0.0;
        g_sum[Cc + threadIdx.x] = 0.0;  g_sumsq[Cc + threadIdx.x] = 0.0;
    }
    __shared__ __align__(16) float sX[64 * C0];
    int tid = threadIdx.x;
    int c = tid & 63, q = tid >> 6;               // 2 cols, 4 row-groups of 16
    size_t row0 = (size_t)blockIdx.x * 64;

    const float4* Xv = (const float4*)(g_agg0 + row0 * C0);
    float4* sv = (float4*)sX;
    #pragma unroll
    for (int i = tid; i < 64 * C0 / 4; i += 256) sv[i] = Xv[i];
    __syncthreads();

    ull accA[16], accB[16];
    #pragma unroll
    for (int r = 0; r < 16; r++) { accA[r] = 0ull; accB[r] = 0ull; }

    const float* sXq = sX + (q * 16) * C0;
    #pragma unroll 4
    for (int kq = 0; kq < C0 / 4; kq++) {
        ull wA0 = g_Wp1[(2 * kq)     * Cc + c];
        ull wA1 = g_Wp1[(2 * kq + 1) * Cc + c];
        ull wB0 = g_Wp1[(2 * kq)     * Cc + c + 64];
        ull wB1 = g_Wp1[(2 * kq + 1) * Cc + c + 64];
        #pragma unroll
        for (int r = 0; r < 16; r++) {
            ulonglong2 xv = *(const ulonglong2*)(sXq + r * C0 + 4 * kq);
            FFMA2(accA[r], xv.x, wA0);
            FFMA2(accA[r], xv.y, wA1);
            FFMA2(accB[r], xv.x, wB0);
            FFMA2(accB[r], xv.y, wB1);
        }
    }
    float bvA = bias[c], bvB = bias[c + 64];
    #pragma unroll
    for (int r = 0; r < 16; r++) {
        size_t row = row0 + q * 16 + r;
        float vA = __uint_as_float((unsigned)accA[r]) + __uint_as_float((unsigned)(accA[r] >> 32)) + bvA;
        float vB = __uint_as_float((unsigned)accB[r]) + __uint_as_float((unsigned)(accB[r] >> 32)) + bvB;
        g_a[row * Cc + c]      = vA;
        g_a[row * Cc + c + 64] = vB;
    }
}

// ---------------- GEMM (layers 2/3): Y = act(X) @ W[128,128] (+U), 64 rows/block ----------------
template <bool ADD_U, bool HALF_OUT>
__device__ __forceinline__ void gemm_body128(
    const float* __restrict__ X, const ull* __restrict__ Wp,
    const float* __restrict__ U,
    const float* __restrict__ scale, const float* __restrict__ shift,
    float* __restrict__ Yf, __half* __restrict__ Yh)
{
    __shared__ __align__(16) float sX[64 * Cc];
    __shared__ float s_sc[Cc], s_sh[Cc];
    int tid = threadIdx.x;
    int c = tid & 63, q = tid >> 6;               // 2 cols, 4 row-groups of 16
    size_t row0 = (size_t)blockIdx.x * 64;

    if (tid < Cc) { s_sc[tid] = scale[tid]; s_sh[tid] = shift[tid]; }
    __syncthreads();

    const float4* Xv = (const float4*)(X + row0 * Cc);
    float4* sv = (float4*)sX;
    #pragma unroll
    for (int i = tid; i < 64 * Cc / 4; i += 256) {
        float4 v = Xv[i];
        int cc = (i * 4) % Cc;
        v.x = fmaxf(0.f, fmaf(v.x, s_sc[cc + 0], s_sh[cc + 0]));
        v.y = fmaxf(0.f, fmaf(v.y, s_sc[cc + 1], s_sh[cc + 1]));
        v.z = fmaxf(0.f, fmaf(v.z, s_sc[cc + 2], s_sh[cc + 2]));
        v.w = fmaxf(0.f, fmaf(v.w, s_sc[cc + 3], s_sh[cc + 3]));
        sv[i] = v;
    }
    __syncthreads();

    ull accA[16], accB[16];
    #pragma unroll
    for (int r = 0; r < 16; r++) { accA[r] = 0ull; accB[r] = 0ull; }

    const float* sXq = sX + (q * 16) * Cc;
    #pragma unroll 4
    for (int kq = 0; kq < Cc / 4; kq++) {
        ull wA0 = Wp[(2 * kq)     * Cc + c];
        ull wA1 = Wp[(2 * kq + 1) * Cc + c];
        ull wB0 = Wp[(2 * kq)     * Cc + c + 64];
        ull wB1 = Wp[(2 * kq + 1) * Cc + c + 64];
        #pragma unroll
        for (int r = 0; r < 16; r++) {
            ulonglong2 xv = *(const ulonglong2*)(sXq + r * Cc + 4 * kq);
            FFMA2(accA[r], xv.x, wA0);
            FFMA2(accA[r], xv.y, wA1);
            FFMA2(accB[r], xv.x, wB0);
            FFMA2(accB[r], xv.y, wB1);
        }
    }

    #pragma unroll
    for (int r = 0; r < 16; r++) {
        size_t row = row0 + q * 16 + r;
        float vA = __uint_as_float((unsigned)accA[r]) + __uint_as_float((unsigned)(accA[r] >> 32));
        float vB = __uint_as_float((unsigned)accB[r]) + __uint_as_float((unsigned)(accB[r] >> 32));
        if (ADD_U) {
            size_t l = row % Ll;
            size_t b = row / ((size_t)Nn * Ll);
            const float* Up = U + (b * Ll + l) * Cc;
            vA += Up[c];
            vB += Up[c + 64];
        }
        if (HALF_OUT) {
            Yh[row * Cc + c]      = __float2half(vA);
            Yh[row * Cc + c + 64] = __float2half(vB);
        } else {
            Yf[row * Cc + c]      = vA;
            Yf[row * Cc + c + 64] = vB;
        }
    }
}

// U = relu(bn(amax)) @ W_up      (upper-half BN params: offset Cc)
__global__ __launch_bounds__(256) void gemmU_kernel(int wsel) {
    const ull* wp = ((wsel == 2) ? g_Wp2 : g_Wp3) + (Cc / 2) * Cc;
    gemm_body128<false, false>(g_amax, wp, nullptr, g_scale + Cc, g_shift + Cc, g_U, nullptr);
}
// hW = relu(bn(a)) @ W_low + U[b]  -> fp16 output for the gather
__global__ __launch_bounds__(256) void gemmM_kernel(int wsel) {
    const ull* wp = (wsel == 2) ? g_Wp2 : g_Wp3;
    gemm_body128<true, true>(g_a, wp, g_U, g_scale, g_shift, nullptr, g_hWh);
}

// ---------------- fused amax + BN stats: ONE pass over g_a ----------------
__global__ void amax_stats_kernel() {
    int c = threadIdx.x;
    float s_a = 0.f, ss_a = 0.f, s_m = 0.f, ss_m = 0.f;
    size_t base = (size_t)blockIdx.x * 8;
    #pragma unroll 1
    for (int j = 0; j < 8; j++) {
        size_t bl = base + j;                 // over B*L = 8192
        size_t b = bl / Ll, l = bl % Ll;
        const float* p = g_a + ((b * Nn) * Ll + l) * Cc + c;
        float m = -3.4e38f;
        #pragma unroll
        for (int n = 0; n < Nn; n++) {
            float v = p[(size_t)n * Ll * Cc];
            s_a += v; ss_a += v * v;
            m = fmaxf(m, v);
        }
        g_amax[bl * Cc + c] = m;
        s_m += m; ss_m += m * m;
    }
    atomicAdd(&g_sum[c],        (double)s_a);
    atomicAdd(&g_sumsq[c],      (double)ss_a);
    atomicAdd(&g_sum[Cc + c],   (double)s_m);
    atomicAdd(&g_sumsq[Cc + c], (double)ss_m);
}

__global__ void bn_kernel(const float* __restrict__ gamma, const float* __restrict__ beta) {
    int c = threadIdx.x;                       // 256
    double cnt = (c < Cc) ? (double)((size_t)Gg * Ll) : (double)((size_t)Bb * Ll);
    double mean = g_sum[c] / cnt;
    double var  = g_sumsq[c] / cnt - mean * mean;
    double inv  = 1.0 / sqrt(var + (double)EPSf);
    double sc   = (double)gamma[c] * inv;
    g_scale[c] = (float)sc;
    g_shift[c] = (float)((double)beta[c] - mean * sc);
}

// ---------------- final: BN+relu+concat+transpose to out [g, 256, l] ----------------
__global__ void final_kernel(float* __restrict__ out) {
    __shared__ float t[32][33];
    int g = blockIdx.z, c0 = blockIdx.y * 32, l0 = blockIdx.x * 32;
    int tx = threadIdx.x, ty = threadIdx.y;
    #pragma unroll
    for (int i = 0; i < 32; i += 8) {
        int l = l0 + ty + i;
        int c = c0 + tx;
        float v;
        if (c < Cc) v = g_a[((size_t)g * Ll + l) * Cc + c];
        else        v = g_amax[((size_t)(g / Nn) * Ll + l) * Cc + (c - Cc)];
        v = fmaxf(0.f, fmaf(v, g_scale[c], g_shift[c]));
        t[ty + i][tx] = v;
    }
    __syncthreads();
    #pragma unroll
    for (int i = 0; i < 32; i += 8) {
        int c = c0 + ty + i;
        int l = l0 + tx;
        out[((size_t)g * C2 + c) * Ll + l] = t[tx][ty + i];
    }
}

// ---------------- launch ----------------
extern "C" void kernel_launch(void* const* d_in, const int* in_sizes, int n_in,
                              void* d_out, int out_size) {
    const float* x  = (const float*)d_in[0];
    const void*  ei = d_in[1];   // int32 or int64, detected on device
    const float *W1 = (const float*)d_in[2],  *b1  = (const float*)d_in[3];
    const float *W2 = (const float*)d_in[4],  *b2  = (const float*)d_in[5];
    const float *W3 = (const float*)d_in[6],  *b3  = (const float*)d_in[7];
    const float *ga1 = (const float*)d_in[8],  *be1 = (const float*)d_in[9];
    const float *ga2 = (const float*)d_in[10], *be2 = (const float*)d_in[11];
    const float *ga3 = (const float*)d_in[12], *be3 = (const float*)d_in[13];
    float* out = (float*)d_out;

    const int rowsGL = Gg * Ll;   // 131072
    const int rowsBL = Bb * Ll;   // 8192

    // setup (launch idx 0..2)
    pack_weights<<<(288 * 128 + 255) / 256, 256>>>(W1, W2, W3);
    graph_build<<<1, 1024>>>((const unsigned int*)ei);
    transpose_x<<<dim3(Ll / 32, C0 / 32, Gg), dim3(32, 8)>>>(x);

    // ---- layer 1 ----
    agg1_kernel<<<rowsGL / 16, 128>>>();
    gemm1_kernel<<<rowsGL / 64, 256>>>(b1);       // also zeroes BN accumulators
    amax_stats_kernel<<<rowsBL / 8, 128>>>();
    bn_kernel<<<1, C2>>>(ga1, be1);

    // ---- layer 2 ----
    gemmU_kernel<<<rowsBL / 64, 256>>>(2);
    gemmM_kernel<<<rowsGL / 64, 256>>>(2);
    agg2_kernel<<<rowsGL / 8, 128>>>(b2);         // also zeroes BN accumulators
    amax_stats_kernel<<<rowsBL / 8, 128>>>();
    bn_kernel<<<1, C2>>>(ga2, be2);

    // ---- layer 3 ----
    gemmU_kernel<<<rowsBL / 64, 256>>>(3);
    gemmM_kernel<<<rowsGL / 64, 256>>>(3);
    agg2_kernel<<<rowsGL / 8, 128>>>(b3);
    amax_stats_kernel<<<rowsBL / 8, 128>>>();
    bn_kernel<<<1, C2>>>(ga3, be3);

    // fused BN + relu + concat + transpose into output layout [b*n, 256, l]
    final_kernel<<<dim3(Ll / 32, C2 / 32, Gg), dim3(32, 8)>>>(out);
}